// round 9
// baseline (speedup 1.0000x reference)
#include <cuda_runtime.h>
#include <cuda_bf16.h>
#include <math.h>

#define Bb_ 2
#define H_ 480
#define W_ 480
#define C_ 32
#define BC 64
#define HP 500
#define WN_ 20
#define NM 40           // 40 ky modes (20 low + 20 high)
#define NPIX (H_*W_)    // 230400
#define NROWS (BC*H_)   // 30720
#define KSPLIT 6        // k_fft_h h-split (480 = 6*80); in-block reduce -> 6 partials
#define NPART 6

typedef unsigned long long u64;

__device__ __forceinline__ u64 pack2(float lo, float hi) {
    u64 r; asm("mov.b64 %0, {%1, %2};" : "=l"(r) : "f"(lo), "f"(hi)); return r;
}
__device__ __forceinline__ void unpack2(u64 v, float& lo, float& hi) {
    asm("mov.b64 {%0, %1}, %2;" : "=f"(lo), "=f"(hi) : "l"(v));
}
__device__ __forceinline__ void fma2(u64& d, u64 a, u64 b) {
    asm("fma.rn.f32x2 %0, %1, %2, %0;" : "+l"(d) : "l"(a), "l"(b));
}

// ---------------- device scratch (static; no allocations) ----------------
__device__ float g_bufA[BC*NPIX];         // 59 MB
__device__ float g_bufB[BC*NPIX];         // 59 MB
__device__ float g_E[BC*NPIX];            // 59 MB
__device__ float g_S1[NROWS*40];          // [row][kz]
__device__ float g_S2p[NPART*BC*1600];    // h-split partials: [sp][bc][1600]
__device__ float g_S2[BC*1600];           // summed: [bc][m][kx][z]
__device__ float g_S3[BC*NM*WN_*2];       // [b][o][m][kx][z]
__device__ float g_T[NROWS*40];           // [bc*480+h][kz] (scaled)
__device__ float g_Wt[W_*40];             // fwd w-twiddle: [w][2kx+z] (z=1 -> -sin)
__device__ float g_Wh[NM*H_*2];           // ky twiddle: [m][h]{cos,sin}
__device__ float g_Gi[40*W_];             // inv w-twiddle rows: [2kx+z][w] (z=1 -> -sin)

__device__ __forceinline__ float gelu_f(float x) {
    return 0.5f * x * (1.0f + erff(x * 0.70710678118654752f));
}

// ---------------- trig tables ----------------
__global__ void k_tables() {
    int t = blockIdx.x * blockDim.x + threadIdx.x;
    if (t < W_ * 40) {
        int c = t % 40, w = t / 40;
        int kx = c >> 1;
        int idx = (kx * w) % 500;
        float s, cc;
        sincospif(2.0f * (float)idx / 500.0f, &s, &cc);
        g_Wt[t] = (c & 1) ? -s : cc;
    }
    if (t < NM * H_) {
        int h = t % H_, m = t / H_;
        int ky = (m < 20) ? m : (460 + m);
        int idx = (ky * h) % 500;
        float s, cc;
        sincospif(2.0f * (float)idx / 500.0f, &s, &cc);
        g_Wh[t * 2] = cc;
        g_Wh[t * 2 + 1] = s;
    }
    if (t < 40 * W_) {
        int w = t % W_, kz = t / W_;
        int kx = kz >> 1;
        int idx = (kx * w) % 500;
        float s, cc;
        sincospif(2.0f * (float)idx / 500.0f, &s, &cc);
        g_Gi[t] = (kz & 1) ? -s : cc;
    }
}

// ---------------- encoder: two tiny MLPs -> A0, E ----------------
__global__ void k_encode(const float* __restrict__ input, const float* __restrict__ src,
                         const float* __restrict__ iw1, const float* __restrict__ ib1,
                         const float* __restrict__ iw2, const float* __restrict__ ib2,
                         const float* __restrict__ ew1, const float* __restrict__ eb1,
                         const float* __restrict__ ew2, const float* __restrict__ eb2,
                         float* __restrict__ A, float* __restrict__ E) {
    int idx = blockIdx.x * blockDim.x + threadIdx.x;
    if (idx >= Bb_ * NPIX) return;
    int w = idx % W_;
    int h = (idx / W_) % H_;
    int b = idx / NPIX;
    float gx = (float)h * (1.0f / 479.0f);
    float gy = (float)w * (1.0f / 479.0f);
    const float* s = src + ((size_t)(b * H_ + h) * W_ + w) * 3;
    float xin[5] = { s[0], s[1], s[2], gx, gy };
    float hid[16];
#pragma unroll
    for (int j = 0; j < 16; j++) {
        float acc = ib1[j];
#pragma unroll
        for (int f = 0; f < 5; f++) acc += xin[f] * iw1[f * 16 + j];
        hid[j] = gelu_f(acc);
    }
    int base = h * W_ + w;
#pragma unroll 4
    for (int c = 0; c < C_; c++) {
        float acc = ib2[c];
#pragma unroll
        for (int j = 0; j < 16; j++) acc += hid[j] * iw2[j * 32 + c];
        A[(b * C_ + c) * NPIX + base] = acc;
    }
    float xe[3] = { input[(b * H_ + h) * W_ + w], gx, gy };
#pragma unroll
    for (int j = 0; j < 16; j++) {
        float acc = eb1[j];
#pragma unroll
        for (int f = 0; f < 3; f++) acc += xe[f] * ew1[f * 16 + j];
        hid[j] = gelu_f(acc);
    }
#pragma unroll 4
    for (int c = 0; c < C_; c++) {
        float acc = eb2[c];
#pragma unroll
        for (int j = 0; j < 16; j++) acc += hid[j] * ew2[j * 32 + c];
        E[(b * C_ + c) * NPIX + base] = acc;
    }
}

// ---------------- stage 1 forward: per-row w-DFT, full K, FFMA2 ----------------
#define FW_BM 96
#define FW_BK 48
__global__ void __launch_bounds__(160) k_fft_w(const float* __restrict__ A,
                                               const float* __restrict__ E,
                                               float* __restrict__ S1) {
    __shared__ float sp[FW_BM][52];
    __shared__ float st[FW_BK][40];
    int tid = threadIdx.x;
    int row0 = blockIdx.x * FW_BM;
    int bc = row0 / H_;
    int hbase = row0 % H_;
    const float* abase = A + (size_t)bc * NPIX + hbase * W_;
    const float* ebase = E + (size_t)bc * NPIX + hbase * W_;
    int tx = tid % 10;
    int ty = tid / 10;
    u64 accP[6][2];
#pragma unroll
    for (int i = 0; i < 6; i++) { accP[i][0] = 0ULL; accP[i][1] = 0ULL; }

    for (int k0 = 0; k0 < W_; k0 += FW_BK) {
        for (int e = tid; e < FW_BM * FW_BK; e += 160) {
            int r = e / FW_BK, kk = e % FW_BK;
            int g = r * W_ + k0 + kk;
            sp[r][kk] = abase[g] * ebase[g];
        }
        {
            const float* wt = g_Wt + k0 * 40;
            for (int e = tid; e < FW_BK * 40; e += 160)
                (&st[0][0])[e] = wt[e];
        }
        __syncthreads();
#pragma unroll
        for (int kk = 0; kk < FW_BK; kk += 4) {
            float avf[6][4];
            ulonglong2 bq[4];
#pragma unroll
            for (int i = 0; i < 6; i++)
                *(float4*)avf[i] = *(const float4*)&sp[ty * 6 + i][kk];
#pragma unroll
            for (int t = 0; t < 4; t++)
                bq[t] = *(const ulonglong2*)&st[kk + t][tx * 4];
#pragma unroll
            for (int t = 0; t < 4; t++) {
#pragma unroll
                for (int i = 0; i < 6; i++) {
                    u64 a2 = pack2(avf[i][t], avf[i][t]);
                    fma2(accP[i][0], a2, bq[t].x);
                    fma2(accP[i][1], a2, bq[t].y);
                }
            }
        }
        __syncthreads();
    }
#pragma unroll
    for (int i = 0; i < 6; i++) {
        int r = row0 + ty * 6 + i;
        float4 v;
        unpack2(accP[i][0], v.x, v.y);
        unpack2(accP[i][1], v.z, v.w);
        *(float4*)&S1[((size_t)r) * 40 + tx * 4] = v;
    }
}

// ---------------- stage 2 forward: ky-DFT, planar FFMA2, in-block reduction ----------------
// grid (BC, KSPLIT); block 800 = 8 subtiles(10h) x 20 m-groups(2) x 5 kx-groups(4)
__global__ void __launch_bounds__(800) k_fft_h(const float* __restrict__ S1,
                                               float* __restrict__ S2p) {
    __shared__ __align__(16) float pool[16160];
    float* s1re = pool;             // [80][20]
    float* s1im = pool + 1600;      // [80][20]
    float* w4   = pool + 3200;      // [40][81][4] {c,c,s,s}; also reused as red buf
    int bc = blockIdx.x;
    int spg = blockIdx.y;
    int t = threadIdx.x;
    int h0 = spg * 80;
    const float* base = S1 + (size_t)(bc * H_) * 40;

    for (int e = t; e < 1600; e += 800) {
        int hh = e / 20, kx = e % 20;
        float2 a = *(const float2*)&base[(h0 + hh) * 40 + kx * 2];
        s1re[hh * 20 + kx] = a.x;
        s1im[hh * 20 + kx] = a.y;
    }
    for (int e = t; e < 3200; e += 800) {
        int m = e / 80, hh = e % 80;
        float2 w = *(const float2*)&g_Wh[(m * H_ + h0 + hh) * 2];
        *(float4*)&w4[(m * 81 + hh) * 4] = make_float4(w.x, w.x, w.y, w.y);
    }
    __syncthreads();

    int sub = t / 100;           // 8 subtiles of 10 h
    int r = t % 100;
    int mg = r / 5;              // 20 m-groups of 2
    int kxg = r % 5;             // 5 kx-groups of 4 kx (2 u64 pairs)
    int m0 = mg * 2;
    u64 AR[2][2], AC[2][2], AS[2][2];
#pragma unroll
    for (int mi = 0; mi < 2; mi++)
#pragma unroll
        for (int j = 0; j < 2; j++) { AR[mi][j] = 0ULL; AC[mi][j] = 0ULL; AS[mi][j] = 0ULL; }

#pragma unroll
    for (int hh = 0; hh < 10; hh++) {
        int hl = sub * 10 + hh;
        ulonglong2 REq = *(const ulonglong2*)&s1re[hl * 20 + kxg * 4];
        ulonglong2 IMq = *(const ulonglong2*)&s1im[hl * 20 + kxg * 4];
#pragma unroll
        for (int mi = 0; mi < 2; mi++) {
            ulonglong2 wq = *(const ulonglong2*)&w4[((m0 + mi) * 81 + hl) * 4]; // {c,c},{s,s}
            fma2(AR[mi][0], REq.x, wq.x);
            fma2(AR[mi][1], REq.y, wq.x);
            fma2(AR[mi][0], IMq.x, wq.y);
            fma2(AR[mi][1], IMq.y, wq.y);
            fma2(AC[mi][0], IMq.x, wq.x);
            fma2(AC[mi][1], IMq.y, wq.x);
            fma2(AS[mi][0], REq.x, wq.y);
            fma2(AS[mi][1], REq.y, wq.y);
        }
    }
    __syncthreads();   // all w4 reads done; safe to overwrite with partials

    // each thread deposits its 16 result floats: j = mi*8 + jj*4 + q
#pragma unroll
    for (int mi = 0; mi < 2; mi++) {
#pragma unroll
        for (int jj = 0; jj < 2; jj++) {
            float ar0, ar1, c0, c1, s0, s1v;
            unpack2(AR[mi][jj], ar0, ar1);
            unpack2(AC[mi][jj], c0, c1);
            unpack2(AS[mi][jj], s0, s1v);
            float4 v = make_float4(ar0, c0 - s0, ar1, c1 - s1v);
            *(float4*)&w4[t * 16 + mi * 8 + jj * 4] = v;
        }
    }
    __syncthreads();

    // tree-reduce the 8 subtiles; thread t handles outputs t and t+800
    size_t obase = ((size_t)spg * BC + bc) * 1600;
#pragma unroll
    for (int gofs = 0; gofs < 2; gofs++) {
        int g = t + gofs * 800;
        int m = g / 40;
        int rem = g % 40;
        int kx2 = rem / 4;       // which 4-float group
        int q = rem % 4;
        int rr = (m / 2) * 5 + kx2 / 2;
        int j = (m % 2) * 8 + (kx2 % 2) * 4 + q;
        float a = 0.f;
#pragma unroll
        for (int sb = 0; sb < 8; sb++)
            a += w4[(sb * 100 + rr) * 16 + j];
        S2p[obase + g] = a;
    }
}

// ---------------- reduce split partials ----------------
__global__ void k_red(const float* __restrict__ P, float* __restrict__ S) {
    int t = blockIdx.x * blockDim.x + threadIdx.x;
    if (t >= BC * 1600) return;
    float a = 0.f;
#pragma unroll
    for (int p = 0; p < NPART; p++) a += P[(size_t)p * BC * 1600 + t];
    S[t] = a;
}

// ---------------- mode mixing ----------------
__global__ void k_mix(const float* __restrict__ S2, const float* __restrict__ fw1,
                      const float* __restrict__ fw2, int l, float* __restrict__ S3) {
    int t = blockIdx.x * blockDim.x + threadIdx.x;
    if (t >= Bb_ * C_ * NM * WN_ * 2) return;
    int z = t & 1;
    int kx = (t >> 1) % WN_;
    int m = ((t >> 1) / WN_) % NM;
    int o = ((t >> 1) / (WN_ * NM)) % C_;
    int b = t / (2 * WN_ * NM * C_);
    const float* wb;
    if (m < 20) wb = fw1 + l * 819200 + o * 800 + m * 40 + kx * 2 + z;
    else        wb = fw2 + l * 819200 + o * 800 + (m - 20) * 40 + kx * 2 + z;
    const float* s2 = S2 + (b * C_) * 1600 + m * (WN_ * 2) + kx * 2 + z;
    float acc = 0.f;
#pragma unroll 8
    for (int i = 0; i < C_; i++)
        acc += s2[i * 1600] * wb[i * 25600];
    S3[((b * C_ + o) * NM + m) * (WN_ * 2) + kx * 2 + z] = acc;
}

// ---------------- stage 1 inverse: ky synthesis (table twiddles) ----------------
__global__ void k_ifft_h(const float* __restrict__ S3, float* __restrict__ T) {
    int t = blockIdx.x * blockDim.x + threadIdx.x;
    if (t >= BC * H_ * WN_) return;
    int kx = t % WN_;
    int h = (t / WN_) % H_;
    int bc = t / (WN_ * H_);
    const float* s3 = S3 + bc * (NM * WN_ * 2) + kx * 2;
    float re = 0.f, im = 0.f;
#pragma unroll
    for (int m = 0; m < NM; m++) {
        float2 wt = *(const float2*)&g_Wh[(m * H_ + h) * 2];
        float ar = s3[m * (WN_ * 2)], ai = s3[m * (WN_ * 2) + 1];
        re += ar * wt.x - ai * wt.y;     // * e^{+i phi}
        im += ar * wt.y + ai * wt.x;
    }
    float sc = ((kx == 0) ? 1.0f : 2.0f) * (1.0f / 250000.0f);
    T[((size_t)bc * H_ + h) * 40 + kx * 2] = re * sc;
    T[((size_t)bc * H_ + h) * 40 + kx * 2 + 1] = im * sc;
}

// ---------------- stage 2 inverse + pointwise conv (augmented GEMM, 8w x 8o FFMA2) ----------------
// block = (wt, h, b), 80 threads; out[32 o][160 w] = [T|cw](32x72) x [Gi; Ain](72x160)
__global__ void __launch_bounds__(80) k_iw_conv(const float* __restrict__ T,
                                                const float* __restrict__ Ain,
                                                const float* __restrict__ cw,
                                                const float* __restrict__ cb, int l,
                                                float* __restrict__ Aout, int do_gelu) {
    __shared__ float R[72][160];
    __shared__ float Lh[72][32];
    int tid = threadIdx.x;
    int wt = blockIdx.x, h = blockIdx.y, b = blockIdx.z;
    int w0 = wt * 160;

    // staging (float4 where possible)
    for (int e = tid; e < 40 * 40; e += 80) {           // Gi: 40 rows x 40 float4
        int kz = e / 40, w4i = e % 40;
        *(float4*)&R[kz][w4i * 4] = *(const float4*)&g_Gi[kz * W_ + w0 + w4i * 4];
    }
    for (int e = tid; e < 32 * 40; e += 80) {           // Ain: 32 rows x 40 float4
        int i = e / 40, w4i = e % 40;
        *(float4*)&R[40 + i][w4i * 4] =
            *(const float4*)&Ain[((size_t)(b * C_ + i)) * NPIX + h * W_ + w0 + w4i * 4];
    }
    for (int e = tid; e < 40 * 32; e += 80) {
        int kz = e % 40, o = e / 40;
        Lh[kz][o] = T[((size_t)(b * C_ + o) * H_ + h) * 40 + kz];
    }
    for (int e = tid; e < 32 * 32; e += 80) {
        int i = e % 32, o = e / 32;
        Lh[40 + i][o] = cw[l * 1024 + o * 32 + i];
    }
    __syncthreads();

    int og = tid / 20;          // 4 o-groups of 8
    int wg = tid % 20;          // 20 w-groups of 8 contiguous pixels
    int o0 = og * 8;
    int wbase = wg * 8;
    u64 acc[8][4];              // [w][o-pair]
#pragma unroll
    for (int p = 0; p < 4; p++) {
        u64 bias = pack2(cb[l * 32 + o0 + 2 * p], cb[l * 32 + o0 + 2 * p + 1]);
#pragma unroll
        for (int w = 0; w < 8; w++) acc[w][p] = bias;
    }

#pragma unroll 4
    for (int k = 0; k < 72; k++) {
        float rw[8];
        *(float4*)&rw[0] = *(const float4*)&R[k][wbase];
        *(float4*)&rw[4] = *(const float4*)&R[k][wbase + 4];
        ulonglong2 lq0 = *(const ulonglong2*)&Lh[k][o0];       // {L0,L1},{L2,L3}
        ulonglong2 lq1 = *(const ulonglong2*)&Lh[k][o0 + 4];   // {L4,L5},{L6,L7}
#pragma unroll
        for (int w = 0; w < 8; w++) {
            u64 rr = pack2(rw[w], rw[w]);
            fma2(acc[w][0], rr, lq0.x);
            fma2(acc[w][1], rr, lq0.y);
            fma2(acc[w][2], rr, lq1.x);
            fma2(acc[w][3], rr, lq1.y);
        }
    }
#pragma unroll
    for (int p = 0; p < 4; p++) {
        float rowA[8], rowB[8];
#pragma unroll
        for (int w = 0; w < 8; w++) {
            unpack2(acc[w][p], rowA[w], rowB[w]);
            if (do_gelu) { rowA[w] = gelu_f(rowA[w]); rowB[w] = gelu_f(rowB[w]); }
        }
        size_t baseA = ((size_t)(b * C_ + o0 + 2 * p)) * NPIX + h * W_ + w0 + wbase;
        size_t baseB = ((size_t)(b * C_ + o0 + 2 * p + 1)) * NPIX + h * W_ + w0 + wbase;
        *(float4*)&Aout[baseA]     = *(float4*)&rowA[0];
        *(float4*)&Aout[baseA + 4] = *(float4*)&rowA[4];
        *(float4*)&Aout[baseB]     = *(float4*)&rowB[0];
        *(float4*)&Aout[baseB + 4] = *(float4*)&rowB[4];
    }
}

// ---------------- final: proj MLP + 3x3 mask conv + combine ----------------
__global__ void k_final(const float* __restrict__ A, const float* __restrict__ input,
                        const float* __restrict__ src,
                        const float* __restrict__ pw1, const float* __restrict__ pb1,
                        const float* __restrict__ pw2, const float* __restrict__ pb2,
                        const float* __restrict__ mw, const float* __restrict__ mb,
                        float* __restrict__ out) {
    int idx = blockIdx.x * blockDim.x + threadIdx.x;
    if (idx >= Bb_ * NPIX) return;
    int w = idx % W_;
    int h = (idx / W_) % H_;
    int b = idx / NPIX;

    const float* ap = A + (size_t)b * C_ * NPIX + h * W_ + w;
    float hid[16];
#pragma unroll
    for (int j = 0; j < 16; j++) hid[j] = pb1[j];
#pragma unroll 4
    for (int i = 0; i < 32; i++) {
        float av = ap[(size_t)i * NPIX];
#pragma unroll
        for (int j = 0; j < 16; j++) hid[j] += av * pw1[i * 16 + j];
    }
    float p0 = pb2[0], p1 = pb2[1];
#pragma unroll
    for (int j = 0; j < 16; j++) {
        float g = gelu_f(hid[j]);
        p0 += g * pw2[j * 2];
        p1 += g * pw2[j * 2 + 1];
    }
    float msum = mb[0];
#pragma unroll
    for (int dy = -1; dy <= 1; dy++) {
#pragma unroll
        for (int dx = -1; dx <= 1; dx++) {
            int hh = h + dy, ww = w + dx;
            if (hh >= 0 && hh < H_ && ww >= 0 && ww < W_)
                msum += input[(b * H_ + hh) * W_ + ww] * mw[(dy + 1) * 3 + (dx + 1)];
        }
    }
    const float* s = src + ((size_t)(b * H_ + h) * W_ + w) * 3;
    out[idx * 2 + 0] = s[1] * msum + p0;
    out[idx * 2 + 1] = s[2] * msum + p1;
}

// ---------------- launcher ----------------
extern "C" void kernel_launch(void* const* d_in, const int* in_sizes, int n_in,
                              void* d_out, int out_size) {
    const float* input = (const float*)d_in[0];
    const float* src   = (const float*)d_in[1];
    const float* iw1   = (const float*)d_in[2];
    const float* ib1   = (const float*)d_in[3];
    const float* iw2   = (const float*)d_in[4];
    const float* ib2   = (const float*)d_in[5];
    const float* ew1   = (const float*)d_in[6];
    const float* eb1   = (const float*)d_in[7];
    const float* ew2   = (const float*)d_in[8];
    const float* eb2   = (const float*)d_in[9];
    const float* fw1   = (const float*)d_in[10];
    const float* fw2   = (const float*)d_in[11];
    const float* cw    = (const float*)d_in[12];
    const float* cb    = (const float*)d_in[13];
    const float* pw1   = (const float*)d_in[14];
    const float* pb1   = (const float*)d_in[15];
    const float* pw2   = (const float*)d_in[16];
    const float* pb2   = (const float*)d_in[17];
    const float* mw    = (const float*)d_in[18];
    const float* mb    = (const float*)d_in[19];

    float *A, *Bp, *E, *S1, *S2p, *S2, *S3, *T;
    cudaGetSymbolAddress((void**)&A,   g_bufA);
    cudaGetSymbolAddress((void**)&Bp,  g_bufB);
    cudaGetSymbolAddress((void**)&E,   g_E);
    cudaGetSymbolAddress((void**)&S1,  g_S1);
    cudaGetSymbolAddress((void**)&S2p, g_S2p);
    cudaGetSymbolAddress((void**)&S2,  g_S2);
    cudaGetSymbolAddress((void**)&S3,  g_S3);
    cudaGetSymbolAddress((void**)&T,   g_T);

    k_tables<<<75, 256>>>();
    k_encode<<<(Bb_ * NPIX + 255) / 256, 256>>>(input, src, iw1, ib1, iw2, ib2,
                                                ew1, eb1, ew2, eb2, A, E);
    for (int l = 0; l < 4; l++) {
        float* Ain  = (l & 1) ? Bp : A;
        float* Aout = (l & 1) ? A  : Bp;
        k_fft_w<<<NROWS / FW_BM, 160>>>(Ain, E, S1);
        dim3 gfh(BC, KSPLIT);
        k_fft_h<<<gfh, 800>>>(S1, S2p);
        k_red<<<(BC * 1600 + 255) / 256, 256>>>(S2p, S2);
        k_mix<<<(Bb_ * C_ * NM * WN_ * 2 + 255) / 256, 256>>>(S2, fw1, fw2, l, S3);
        k_ifft_h<<<(BC * H_ * WN_ + 255) / 256, 256>>>(S3, T);
        dim3 g(W_ / 160, H_, Bb_);
        k_iw_conv<<<g, 80>>>(T, Ain, cw, cb, l, Aout, (l < 3) ? 1 : 0);
    }
    k_final<<<(Bb_ * NPIX + 255) / 256, 256>>>(A, input, src, pw1, pb1, pw2, pb2,
                                               mw, mb, (float*)d_out);
}

// round 10
// speedup vs baseline: 1.1677x; 1.1677x over previous
#include <cuda_runtime.h>
#include <cuda_bf16.h>
#include <math.h>

#define Bb_ 2
#define H_ 480
#define W_ 480
#define C_ 32
#define BC 64
#define HP 500
#define WN_ 20
#define NM 40           // 40 ky modes (20 low + 20 high)
#define NPIX (H_*W_)    // 230400
#define NROWS (BC*H_)   // 30720
#define KSPLIT 6        // k_fft_h h-split (480 = 6*80); in-block reduce -> 6 partials
#define NPART 6

typedef unsigned long long u64;

__device__ __forceinline__ u64 pack2(float lo, float hi) {
    u64 r; asm("mov.b64 %0, {%1, %2};" : "=l"(r) : "f"(lo), "f"(hi)); return r;
}
__device__ __forceinline__ void unpack2(u64 v, float& lo, float& hi) {
    asm("mov.b64 {%0, %1}, %2;" : "=f"(lo), "=f"(hi) : "l"(v));
}
__device__ __forceinline__ void fma2(u64& d, u64 a, u64 b) {
    asm("fma.rn.f32x2 %0, %1, %2, %0;" : "+l"(d) : "l"(a), "l"(b));
}

// ---------------- device scratch (static; no allocations) ----------------
__device__ float g_bufA[BC*NPIX];         // 59 MB
__device__ float g_bufB[BC*NPIX];         // 59 MB
__device__ float g_E[BC*NPIX];            // 59 MB
__device__ float g_S1[NROWS*40];          // [row][kz]
__device__ float g_S2p[NPART*BC*1600];    // h-split partials: [sp][bc][1600]
__device__ float g_S2[BC*1600];           // summed: [bc][m][kx][z]
__device__ float g_S3[BC*NM*WN_*2];       // [b][o][m][kx][z]
__device__ float g_T[NROWS*40];           // [bc*480+h][kz] (scaled)
__device__ float g_Wt[W_*40];             // fwd w-twiddle: [w][2kx+z] (z=1 -> -sin)
__device__ float g_Wh[NM*H_*2];           // ky twiddle: [m][h]{cos,sin}
__device__ float g_Gi[40*W_];             // inv w-twiddle rows: [2kx+z][w] (z=1 -> -sin)

__device__ __forceinline__ float gelu_f(float x) {
    return 0.5f * x * (1.0f + erff(x * 0.70710678118654752f));
}

// ---------------- trig tables ----------------
__global__ void k_tables() {
    int t = blockIdx.x * blockDim.x + threadIdx.x;
    if (t < W_ * 40) {
        int c = t % 40, w = t / 40;
        int kx = c >> 1;
        int idx = (kx * w) % 500;
        float s, cc;
        sincospif(2.0f * (float)idx / 500.0f, &s, &cc);
        g_Wt[t] = (c & 1) ? -s : cc;
    }
    if (t < NM * H_) {
        int h = t % H_, m = t / H_;
        int ky = (m < 20) ? m : (460 + m);
        int idx = (ky * h) % 500;
        float s, cc;
        sincospif(2.0f * (float)idx / 500.0f, &s, &cc);
        g_Wh[t * 2] = cc;
        g_Wh[t * 2 + 1] = s;
    }
    if (t < 40 * W_) {
        int w = t % W_, kz = t / W_;
        int kx = kz >> 1;
        int idx = (kx * w) % 500;
        float s, cc;
        sincospif(2.0f * (float)idx / 500.0f, &s, &cc);
        g_Gi[t] = (kz & 1) ? -s : cc;
    }
}

// ---------------- encoder: two tiny MLPs -> A0, E ----------------
__global__ void k_encode(const float* __restrict__ input, const float* __restrict__ src,
                         const float* __restrict__ iw1, const float* __restrict__ ib1,
                         const float* __restrict__ iw2, const float* __restrict__ ib2,
                         const float* __restrict__ ew1, const float* __restrict__ eb1,
                         const float* __restrict__ ew2, const float* __restrict__ eb2,
                         float* __restrict__ A, float* __restrict__ E) {
    int idx = blockIdx.x * blockDim.x + threadIdx.x;
    if (idx >= Bb_ * NPIX) return;
    int w = idx % W_;
    int h = (idx / W_) % H_;
    int b = idx / NPIX;
    float gx = (float)h * (1.0f / 479.0f);
    float gy = (float)w * (1.0f / 479.0f);
    const float* s = src + ((size_t)(b * H_ + h) * W_ + w) * 3;
    float xin[5] = { s[0], s[1], s[2], gx, gy };
    float hid[16];
#pragma unroll
    for (int j = 0; j < 16; j++) {
        float acc = ib1[j];
#pragma unroll
        for (int f = 0; f < 5; f++) acc += xin[f] * iw1[f * 16 + j];
        hid[j] = gelu_f(acc);
    }
    int base = h * W_ + w;
#pragma unroll 4
    for (int c = 0; c < C_; c++) {
        float acc = ib2[c];
#pragma unroll
        for (int j = 0; j < 16; j++) acc += hid[j] * iw2[j * 32 + c];
        A[(b * C_ + c) * NPIX + base] = acc;
    }
    float xe[3] = { input[(b * H_ + h) * W_ + w], gx, gy };
#pragma unroll
    for (int j = 0; j < 16; j++) {
        float acc = eb1[j];
#pragma unroll
        for (int f = 0; f < 3; f++) acc += xe[f] * ew1[f * 16 + j];
        hid[j] = gelu_f(acc);
    }
#pragma unroll 4
    for (int c = 0; c < C_; c++) {
        float acc = eb2[c];
#pragma unroll
        for (int j = 0; j < 16; j++) acc += hid[j] * ew2[j * 32 + c];
        E[(b * C_ + c) * NPIX + base] = acc;
    }
}

// ---------------- stage 1 forward: per-row w-DFT, full K, FFMA2 ----------------
#define FW_BM 96
#define FW_BK 48
__global__ void __launch_bounds__(160) k_fft_w(const float* __restrict__ A,
                                               const float* __restrict__ E,
                                               float* __restrict__ S1) {
    __shared__ float sp[FW_BM][52];
    __shared__ float st[FW_BK][40];
    int tid = threadIdx.x;
    int row0 = blockIdx.x * FW_BM;
    int bc = row0 / H_;
    int hbase = row0 % H_;
    const float* abase = A + (size_t)bc * NPIX + hbase * W_;
    const float* ebase = E + (size_t)bc * NPIX + hbase * W_;
    int tx = tid % 10;
    int ty = tid / 10;
    u64 accP[6][2];
#pragma unroll
    for (int i = 0; i < 6; i++) { accP[i][0] = 0ULL; accP[i][1] = 0ULL; }

    for (int k0 = 0; k0 < W_; k0 += FW_BK) {
        for (int e = tid; e < FW_BM * FW_BK; e += 160) {
            int r = e / FW_BK, kk = e % FW_BK;
            int g = r * W_ + k0 + kk;
            sp[r][kk] = abase[g] * ebase[g];
        }
        {
            const float* wt = g_Wt + k0 * 40;
            for (int e = tid; e < FW_BK * 40; e += 160)
                (&st[0][0])[e] = wt[e];
        }
        __syncthreads();
#pragma unroll
        for (int kk = 0; kk < FW_BK; kk += 4) {
            float avf[6][4];
            ulonglong2 bq[4];
#pragma unroll
            for (int i = 0; i < 6; i++)
                *(float4*)avf[i] = *(const float4*)&sp[ty * 6 + i][kk];
#pragma unroll
            for (int t = 0; t < 4; t++)
                bq[t] = *(const ulonglong2*)&st[kk + t][tx * 4];
#pragma unroll
            for (int t = 0; t < 4; t++) {
#pragma unroll
                for (int i = 0; i < 6; i++) {
                    u64 a2 = pack2(avf[i][t], avf[i][t]);
                    fma2(accP[i][0], a2, bq[t].x);
                    fma2(accP[i][1], a2, bq[t].y);
                }
            }
        }
        __syncthreads();
    }
#pragma unroll
    for (int i = 0; i < 6; i++) {
        int r = row0 + ty * 6 + i;
        float4 v;
        unpack2(accP[i][0], v.x, v.y);
        unpack2(accP[i][1], v.z, v.w);
        *(float4*)&S1[((size_t)r) * 40 + tx * 4] = v;
    }
}

// ---------------- stage 2 forward: ky-DFT, planar FFMA2, in-block reduction ----------------
// grid (BC, KSPLIT); block 800 = 8 subtiles(10h) x 20 m-groups(2) x 5 kx-groups(4)
__global__ void __launch_bounds__(800) k_fft_h(const float* __restrict__ S1,
                                               float* __restrict__ S2p) {
    __shared__ __align__(16) float pool[16160];
    float* s1re = pool;             // [80][20]
    float* s1im = pool + 1600;      // [80][20]
    float* w4   = pool + 3200;      // [40][81][4] {c,c,s,s}; also reused as red buf
    int bc = blockIdx.x;
    int spg = blockIdx.y;
    int t = threadIdx.x;
    int h0 = spg * 80;
    const float* base = S1 + (size_t)(bc * H_) * 40;

    for (int e = t; e < 1600; e += 800) {
        int hh = e / 20, kx = e % 20;
        float2 a = *(const float2*)&base[(h0 + hh) * 40 + kx * 2];
        s1re[hh * 20 + kx] = a.x;
        s1im[hh * 20 + kx] = a.y;
    }
    for (int e = t; e < 3200; e += 800) {
        int m = e / 80, hh = e % 80;
        float2 w = *(const float2*)&g_Wh[(m * H_ + h0 + hh) * 2];
        *(float4*)&w4[(m * 81 + hh) * 4] = make_float4(w.x, w.x, w.y, w.y);
    }
    __syncthreads();

    int sub = t / 100;           // 8 subtiles of 10 h
    int r = t % 100;
    int mg = r / 5;              // 20 m-groups of 2
    int kxg = r % 5;             // 5 kx-groups of 4 kx (2 u64 pairs)
    int m0 = mg * 2;
    u64 AR[2][2], AC[2][2], AS[2][2];
#pragma unroll
    for (int mi = 0; mi < 2; mi++)
#pragma unroll
        for (int j = 0; j < 2; j++) { AR[mi][j] = 0ULL; AC[mi][j] = 0ULL; AS[mi][j] = 0ULL; }

#pragma unroll
    for (int hh = 0; hh < 10; hh++) {
        int hl = sub * 10 + hh;
        ulonglong2 REq = *(const ulonglong2*)&s1re[hl * 20 + kxg * 4];
        ulonglong2 IMq = *(const ulonglong2*)&s1im[hl * 20 + kxg * 4];
#pragma unroll
        for (int mi = 0; mi < 2; mi++) {
            ulonglong2 wq = *(const ulonglong2*)&w4[((m0 + mi) * 81 + hl) * 4]; // {c,c},{s,s}
            fma2(AR[mi][0], REq.x, wq.x);
            fma2(AR[mi][1], REq.y, wq.x);
            fma2(AR[mi][0], IMq.x, wq.y);
            fma2(AR[mi][1], IMq.y, wq.y);
            fma2(AC[mi][0], IMq.x, wq.x);
            fma2(AC[mi][1], IMq.y, wq.x);
            fma2(AS[mi][0], REq.x, wq.y);
            fma2(AS[mi][1], REq.y, wq.y);
        }
    }
    __syncthreads();   // all w4 reads done; safe to overwrite with partials

    // each thread deposits its 16 result floats: j = mi*8 + jj*4 + q
#pragma unroll
    for (int mi = 0; mi < 2; mi++) {
#pragma unroll
        for (int jj = 0; jj < 2; jj++) {
            float ar0, ar1, c0, c1, s0, s1v;
            unpack2(AR[mi][jj], ar0, ar1);
            unpack2(AC[mi][jj], c0, c1);
            unpack2(AS[mi][jj], s0, s1v);
            float4 v = make_float4(ar0, c0 - s0, ar1, c1 - s1v);
            *(float4*)&w4[t * 16 + mi * 8 + jj * 4] = v;
        }
    }
    __syncthreads();

    // tree-reduce the 8 subtiles; thread t handles outputs t and t+800
    size_t obase = ((size_t)spg * BC + bc) * 1600;
#pragma unroll
    for (int gofs = 0; gofs < 2; gofs++) {
        int g = t + gofs * 800;
        int m = g / 40;
        int rem = g % 40;
        int kx2 = rem / 4;       // which 4-float group
        int q = rem % 4;
        int rr = (m / 2) * 5 + kx2 / 2;
        int j = (m % 2) * 8 + (kx2 % 2) * 4 + q;
        float a = 0.f;
#pragma unroll
        for (int sb = 0; sb < 8; sb++)
            a += w4[(sb * 100 + rr) * 16 + j];
        S2p[obase + g] = a;
    }
}

// ---------------- reduce split partials ----------------
__global__ void k_red(const float* __restrict__ P, float* __restrict__ S) {
    int t = blockIdx.x * blockDim.x + threadIdx.x;
    if (t >= BC * 1600) return;
    float a = 0.f;
#pragma unroll
    for (int p = 0; p < NPART; p++) a += P[(size_t)p * BC * 1600 + t];
    S[t] = a;
}

// ---------------- mode mixing ----------------
__global__ void k_mix(const float* __restrict__ S2, const float* __restrict__ fw1,
                      const float* __restrict__ fw2, int l, float* __restrict__ S3) {
    int t = blockIdx.x * blockDim.x + threadIdx.x;
    if (t >= Bb_ * C_ * NM * WN_ * 2) return;
    int z = t & 1;
    int kx = (t >> 1) % WN_;
    int m = ((t >> 1) / WN_) % NM;
    int o = ((t >> 1) / (WN_ * NM)) % C_;
    int b = t / (2 * WN_ * NM * C_);
    const float* wb;
    if (m < 20) wb = fw1 + l * 819200 + o * 800 + m * 40 + kx * 2 + z;
    else        wb = fw2 + l * 819200 + o * 800 + (m - 20) * 40 + kx * 2 + z;
    const float* s2 = S2 + (b * C_) * 1600 + m * (WN_ * 2) + kx * 2 + z;
    float acc = 0.f;
#pragma unroll 8
    for (int i = 0; i < C_; i++)
        acc += s2[i * 1600] * wb[i * 25600];
    S3[((b * C_ + o) * NM + m) * (WN_ * 2) + kx * 2 + z] = acc;
}

// ---------------- stage 1 inverse: ky synthesis (table twiddles) ----------------
__global__ void k_ifft_h(const float* __restrict__ S3, float* __restrict__ T) {
    int t = blockIdx.x * blockDim.x + threadIdx.x;
    if (t >= BC * H_ * WN_) return;
    int kx = t % WN_;
    int h = (t / WN_) % H_;
    int bc = t / (WN_ * H_);
    const float* s3 = S3 + bc * (NM * WN_ * 2) + kx * 2;
    float re = 0.f, im = 0.f;
#pragma unroll
    for (int m = 0; m < NM; m++) {
        float2 wt = *(const float2*)&g_Wh[(m * H_ + h) * 2];
        float ar = s3[m * (WN_ * 2)], ai = s3[m * (WN_ * 2) + 1];
        re += ar * wt.x - ai * wt.y;     // * e^{+i phi}
        im += ar * wt.y + ai * wt.x;
    }
    float sc = ((kx == 0) ? 1.0f : 2.0f) * (1.0f / 250000.0f);
    T[((size_t)bc * H_ + h) * 40 + kx * 2] = re * sc;
    T[((size_t)bc * H_ + h) * 40 + kx * 2 + 1] = im * sc;
}

// ---------------- stage 2 inverse + pointwise conv (augmented GEMM, 4w x 8o FFMA2) ----------------
// block = (wt, h, b), 160 threads; out[32 o][160 w] = [T|cw](32x72) x [Gi; Ain](72x160)
__global__ void __launch_bounds__(160) k_iw_conv(const float* __restrict__ T,
                                                 const float* __restrict__ Ain,
                                                 const float* __restrict__ cw,
                                                 const float* __restrict__ cb, int l,
                                                 float* __restrict__ Aout, int do_gelu) {
    __shared__ float R[72][160];
    __shared__ float Lh[72][32];
    int tid = threadIdx.x;
    int wt = blockIdx.x, h = blockIdx.y, b = blockIdx.z;
    int w0 = wt * 160;

    // staging with float4 loads
    for (int e = tid; e < 40 * 40; e += 160) {          // Gi: 40 rows x 40 float4
        int kz = e / 40, w4i = e % 40;
        *(float4*)&R[kz][w4i * 4] = *(const float4*)&g_Gi[kz * W_ + w0 + w4i * 4];
    }
    for (int e = tid; e < 32 * 40; e += 160) {          // Ain: 32 rows x 40 float4
        int i = e / 40, w4i = e % 40;
        *(float4*)&R[40 + i][w4i * 4] =
            *(const float4*)&Ain[((size_t)(b * C_ + i)) * NPIX + h * W_ + w0 + w4i * 4];
    }
    for (int e = tid; e < 40 * 32; e += 160) {
        int kz = e % 40, o = e / 40;
        Lh[kz][o] = T[((size_t)(b * C_ + o) * H_ + h) * 40 + kz];
    }
    for (int e = tid; e < 32 * 32; e += 160) {
        int i = e % 32, o = e / 32;
        Lh[40 + i][o] = cw[l * 1024 + o * 32 + i];
    }
    __syncthreads();

    int og = tid / 40;          // 4 o-groups of 8
    int wl = tid % 40;          // 4 pixels: wl + 40*q
    int o0 = og * 8;
    u64 aP[4][4];               // [q][o-pair]
#pragma unroll
    for (int p = 0; p < 4; p++) {
        u64 bias = pack2(cb[l * 32 + o0 + 2 * p], cb[l * 32 + o0 + 2 * p + 1]);
#pragma unroll
        for (int q = 0; q < 4; q++) aP[q][p] = bias;
    }

#pragma unroll 4
    for (int k = 0; k < 72; k++) {
        u64 r2[4];
#pragma unroll
        for (int q = 0; q < 4; q++) {
            float rv = R[k][wl + 40 * q];
            r2[q] = pack2(rv, rv);
        }
        ulonglong2 lq0 = *(const ulonglong2*)&Lh[k][o0];       // {L0,L1},{L2,L3}
        ulonglong2 lq1 = *(const ulonglong2*)&Lh[k][o0 + 4];   // {L4,L5},{L6,L7}
#pragma unroll
        for (int q = 0; q < 4; q++) {
            fma2(aP[q][0], r2[q], lq0.x);
            fma2(aP[q][1], r2[q], lq0.y);
            fma2(aP[q][2], r2[q], lq1.x);
            fma2(aP[q][3], r2[q], lq1.y);
        }
    }
#pragma unroll
    for (int p = 0; p < 4; p++) {
        size_t baseA = ((size_t)(b * C_ + o0 + 2 * p)) * NPIX + h * W_ + w0;
        size_t baseB = ((size_t)(b * C_ + o0 + 2 * p + 1)) * NPIX + h * W_ + w0;
#pragma unroll
        for (int q = 0; q < 4; q++) {
            float va, vb;
            unpack2(aP[q][p], va, vb);
            if (do_gelu) { va = gelu_f(va); vb = gelu_f(vb); }
            Aout[baseA + wl + 40 * q] = va;
            Aout[baseB + wl + 40 * q] = vb;
        }
    }
}

// ---------------- final: proj MLP + 3x3 mask conv + combine ----------------
__global__ void k_final(const float* __restrict__ A, const float* __restrict__ input,
                        const float* __restrict__ src,
                        const float* __restrict__ pw1, const float* __restrict__ pb1,
                        const float* __restrict__ pw2, const float* __restrict__ pb2,
                        const float* __restrict__ mw, const float* __restrict__ mb,
                        float* __restrict__ out) {
    int idx = blockIdx.x * blockDim.x + threadIdx.x;
    if (idx >= Bb_ * NPIX) return;
    int w = idx % W_;
    int h = (idx / W_) % H_;
    int b = idx / NPIX;

    const float* ap = A + (size_t)b * C_ * NPIX + h * W_ + w;
    float hid[16];
#pragma unroll
    for (int j = 0; j < 16; j++) hid[j] = pb1[j];
#pragma unroll 4
    for (int i = 0; i < 32; i++) {
        float av = ap[(size_t)i * NPIX];
#pragma unroll
        for (int j = 0; j < 16; j++) hid[j] += av * pw1[i * 16 + j];
    }
    float p0 = pb2[0], p1 = pb2[1];
#pragma unroll
    for (int j = 0; j < 16; j++) {
        float g = gelu_f(hid[j]);
        p0 += g * pw2[j * 2];
        p1 += g * pw2[j * 2 + 1];
    }
    float msum = mb[0];
#pragma unroll
    for (int dy = -1; dy <= 1; dy++) {
#pragma unroll
        for (int dx = -1; dx <= 1; dx++) {
            int hh = h + dy, ww = w + dx;
            if (hh >= 0 && hh < H_ && ww >= 0 && ww < W_)
                msum += input[(b * H_ + hh) * W_ + ww] * mw[(dy + 1) * 3 + (dx + 1)];
        }
    }
    const float* s = src + ((size_t)(b * H_ + h) * W_ + w) * 3;
    out[idx * 2 + 0] = s[1] * msum + p0;
    out[idx * 2 + 1] = s[2] * msum + p1;
}

// ---------------- launcher ----------------
extern "C" void kernel_launch(void* const* d_in, const int* in_sizes, int n_in,
                              void* d_out, int out_size) {
    const float* input = (const float*)d_in[0];
    const float* src   = (const float*)d_in[1];
    const float* iw1   = (const float*)d_in[2];
    const float* ib1   = (const float*)d_in[3];
    const float* iw2   = (const float*)d_in[4];
    const float* ib2   = (const float*)d_in[5];
    const float* ew1   = (const float*)d_in[6];
    const float* eb1   = (const float*)d_in[7];
    const float* ew2   = (const float*)d_in[8];
    const float* eb2   = (const float*)d_in[9];
    const float* fw1   = (const float*)d_in[10];
    const float* fw2   = (const float*)d_in[11];
    const float* cw    = (const float*)d_in[12];
    const float* cb    = (const float*)d_in[13];
    const float* pw1   = (const float*)d_in[14];
    const float* pb1   = (const float*)d_in[15];
    const float* pw2   = (const float*)d_in[16];
    const float* pb2   = (const float*)d_in[17];
    const float* mw    = (const float*)d_in[18];
    const float* mb    = (const float*)d_in[19];

    float *A, *Bp, *E, *S1, *S2p, *S2, *S3, *T;
    cudaGetSymbolAddress((void**)&A,   g_bufA);
    cudaGetSymbolAddress((void**)&Bp,  g_bufB);
    cudaGetSymbolAddress((void**)&E,   g_E);
    cudaGetSymbolAddress((void**)&S1,  g_S1);
    cudaGetSymbolAddress((void**)&S2p, g_S2p);
    cudaGetSymbolAddress((void**)&S2,  g_S2);
    cudaGetSymbolAddress((void**)&S3,  g_S3);
    cudaGetSymbolAddress((void**)&T,   g_T);

    k_tables<<<75, 256>>>();
    k_encode<<<(Bb_ * NPIX + 255) / 256, 256>>>(input, src, iw1, ib1, iw2, ib2,
                                                ew1, eb1, ew2, eb2, A, E);
    for (int l = 0; l < 4; l++) {
        float* Ain  = (l & 1) ? Bp : A;
        float* Aout = (l & 1) ? A  : Bp;
        k_fft_w<<<NROWS / FW_BM, 160>>>(Ain, E, S1);
        dim3 gfh(BC, KSPLIT);
        k_fft_h<<<gfh, 800>>>(S1, S2p);
        k_red<<<(BC * 1600 + 255) / 256, 256>>>(S2p, S2);
        k_mix<<<(Bb_ * C_ * NM * WN_ * 2 + 255) / 256, 256>>>(S2, fw1, fw2, l, S3);
        k_ifft_h<<<(BC * H_ * WN_ + 255) / 256, 256>>>(S3, T);
        dim3 g(W_ / 160, H_, Bb_);
        k_iw_conv<<<g, 160>>>(T, Ain, cw, cb, l, Aout, (l < 3) ? 1 : 0);
    }
    k_final<<<(Bb_ * NPIX + 255) / 256, 256>>>(A, input, src, pw1, pb1, pw2, pb2,
                                               mw, mb, (float*)d_out);
}

// round 11
// speedup vs baseline: 1.3346x; 1.1429x over previous
#include <cuda_runtime.h>
#include <cuda_bf16.h>
#include <math.h>

#define Bb_ 2
#define H_ 480
#define W_ 480
#define C_ 32
#define BC 64
#define HP 500
#define WN_ 20
#define NM 40           // 40 ky modes (20 low + 20 high)
#define NPIX (H_*W_)    // 230400
#define NROWS (BC*H_)   // 30720
#define KSPLIT 6        // k_fft_h h-split (480 = 6*80); in-block reduce -> 6 partials
#define NPART 6

typedef unsigned long long u64;

__device__ __forceinline__ u64 pack2(float lo, float hi) {
    u64 r; asm("mov.b64 %0, {%1, %2};" : "=l"(r) : "f"(lo), "f"(hi)); return r;
}
__device__ __forceinline__ void unpack2(u64 v, float& lo, float& hi) {
    asm("mov.b64 {%0, %1}, %2;" : "=f"(lo), "=f"(hi) : "l"(v));
}
__device__ __forceinline__ void fma2(u64& d, u64 a, u64 b) {
    asm("fma.rn.f32x2 %0, %1, %2, %0;" : "+l"(d) : "l"(a), "l"(b));
}

// ---------------- device scratch (static; no allocations) ----------------
__device__ float g_bufA[BC*NPIX];         // 59 MB
__device__ float g_bufB[BC*NPIX];         // 59 MB
__device__ float g_E[BC*NPIX];            // 59 MB
__device__ float g_S1[2*NROWS*40];        // w-split partials: [half][row][kz]
__device__ float g_S2p[NPART*BC*1600];    // h-split partials: [sp][bc][1600]
__device__ float g_S2[BC*1600];           // summed: [bc][m][kx][z]
__device__ float g_S3[BC*NM*WN_*2];       // [b][o][m][kx][z]
__device__ float g_T[NROWS*40];           // [bc*480+h][kz] (scaled)
__device__ float g_Wt[W_*40];             // fwd w-twiddle: [w][2kx+z] (z=1 -> -sin)
__device__ float g_Wh[NM*H_*2];           // ky twiddle: [m][h]{cos,sin}
__device__ float g_Gi[40*W_];             // inv w-twiddle rows: [2kx+z][w] (z=1 -> -sin)

__device__ __forceinline__ float gelu_f(float x) {
    return 0.5f * x * (1.0f + erff(x * 0.70710678118654752f));
}

// ---------------- trig tables ----------------
__global__ void k_tables() {
    int t = blockIdx.x * blockDim.x + threadIdx.x;
    if (t < W_ * 40) {
        int c = t % 40, w = t / 40;
        int kx = c >> 1;
        int idx = (kx * w) % 500;
        float s, cc;
        sincospif(2.0f * (float)idx / 500.0f, &s, &cc);
        g_Wt[t] = (c & 1) ? -s : cc;
    }
    if (t < NM * H_) {
        int h = t % H_, m = t / H_;
        int ky = (m < 20) ? m : (460 + m);
        int idx = (ky * h) % 500;
        float s, cc;
        sincospif(2.0f * (float)idx / 500.0f, &s, &cc);
        g_Wh[t * 2] = cc;
        g_Wh[t * 2 + 1] = s;
    }
    if (t < 40 * W_) {
        int w = t % W_, kz = t / W_;
        int kx = kz >> 1;
        int idx = (kx * w) % 500;
        float s, cc;
        sincospif(2.0f * (float)idx / 500.0f, &s, &cc);
        g_Gi[t] = (kz & 1) ? -s : cc;
    }
}

// ---------------- encoder: two tiny MLPs -> A0, E ----------------
__global__ void k_encode(const float* __restrict__ input, const float* __restrict__ src,
                         const float* __restrict__ iw1, const float* __restrict__ ib1,
                         const float* __restrict__ iw2, const float* __restrict__ ib2,
                         const float* __restrict__ ew1, const float* __restrict__ eb1,
                         const float* __restrict__ ew2, const float* __restrict__ eb2,
                         float* __restrict__ A, float* __restrict__ E) {
    int idx = blockIdx.x * blockDim.x + threadIdx.x;
    if (idx >= Bb_ * NPIX) return;
    int w = idx % W_;
    int h = (idx / W_) % H_;
    int b = idx / NPIX;
    float gx = (float)h * (1.0f / 479.0f);
    float gy = (float)w * (1.0f / 479.0f);
    const float* s = src + ((size_t)(b * H_ + h) * W_ + w) * 3;
    float xin[5] = { s[0], s[1], s[2], gx, gy };
    float hid[16];
#pragma unroll
    for (int j = 0; j < 16; j++) {
        float acc = ib1[j];
#pragma unroll
        for (int f = 0; f < 5; f++) acc += xin[f] * iw1[f * 16 + j];
        hid[j] = gelu_f(acc);
    }
    int base = h * W_ + w;
#pragma unroll 4
    for (int c = 0; c < C_; c++) {
        float acc = ib2[c];
#pragma unroll
        for (int j = 0; j < 16; j++) acc += hid[j] * iw2[j * 32 + c];
        A[(b * C_ + c) * NPIX + base] = acc;
    }
    float xe[3] = { input[(b * H_ + h) * W_ + w], gx, gy };
#pragma unroll
    for (int j = 0; j < 16; j++) {
        float acc = eb1[j];
#pragma unroll
        for (int f = 0; f < 3; f++) acc += xe[f] * ew1[f * 16 + j];
        hid[j] = gelu_f(acc);
    }
#pragma unroll 4
    for (int c = 0; c < C_; c++) {
        float acc = eb2[c];
#pragma unroll
        for (int j = 0; j < 16; j++) acc += hid[j] * ew2[j * 32 + c];
        E[(b * C_ + c) * NPIX + base] = acc;
    }
}

// ---------------- stage 1 forward: per-row w-DFT, 2-way K-split, FFMA2 ----------------
#define FW_BM 96
#define FW_BK 48
__global__ void __launch_bounds__(160) k_fft_w(const float* __restrict__ A,
                                               const float* __restrict__ E,
                                               float* __restrict__ S1p) {
    __shared__ float sp[FW_BM][52];
    __shared__ float st[FW_BK][40];
    int tid = threadIdx.x;
    int half = blockIdx.y;
    int row0 = blockIdx.x * FW_BM;
    int bc = row0 / H_;
    int hbase = row0 % H_;
    const float* abase = A + (size_t)bc * NPIX + hbase * W_ + half * 240;
    const float* ebase = E + (size_t)bc * NPIX + hbase * W_ + half * 240;
    int tx = tid % 10;
    int ty = tid / 10;
    u64 accP[6][2];
#pragma unroll
    for (int i = 0; i < 6; i++) { accP[i][0] = 0ULL; accP[i][1] = 0ULL; }

    for (int k0 = 0; k0 < 240; k0 += FW_BK) {
        for (int e = tid; e < FW_BM * FW_BK; e += 160) {
            int r = e / FW_BK, kk = e % FW_BK;
            int g = r * W_ + k0 + kk;
            sp[r][kk] = abase[g] * ebase[g];
        }
        {
            const float* wt = g_Wt + (half * 240 + k0) * 40;
            for (int e = tid; e < FW_BK * 40; e += 160)
                (&st[0][0])[e] = wt[e];
        }
        __syncthreads();
#pragma unroll
        for (int kk = 0; kk < FW_BK; kk += 4) {
            float avf[6][4];
            ulonglong2 bq[4];
#pragma unroll
            for (int i = 0; i < 6; i++)
                *(float4*)avf[i] = *(const float4*)&sp[ty * 6 + i][kk];
#pragma unroll
            for (int t = 0; t < 4; t++)
                bq[t] = *(const ulonglong2*)&st[kk + t][tx * 4];
#pragma unroll
            for (int t = 0; t < 4; t++) {
#pragma unroll
                for (int i = 0; i < 6; i++) {
                    u64 a2 = pack2(avf[i][t], avf[i][t]);
                    fma2(accP[i][0], a2, bq[t].x);
                    fma2(accP[i][1], a2, bq[t].y);
                }
            }
        }
        __syncthreads();
    }
#pragma unroll
    for (int i = 0; i < 6; i++) {
        int r = row0 + ty * 6 + i;
        float4 v;
        unpack2(accP[i][0], v.x, v.y);
        unpack2(accP[i][1], v.z, v.w);
        *(float4*)&S1p[((size_t)half * NROWS + r) * 40 + tx * 4] = v;
    }
}

// ---------------- stage 2 forward: ky-DFT, planar FFMA2, in-block reduction ----------------
// grid (BC, KSPLIT); block 800 = 8 subtiles(10h) x 20 m-groups(2) x 5 kx-groups(4)
__global__ void __launch_bounds__(800) k_fft_h(const float* __restrict__ S1p,
                                               float* __restrict__ S2p) {
    __shared__ __align__(16) float pool[16160];
    float* s1re = pool;             // [80][20]
    float* s1im = pool + 1600;      // [80][20]
    float* w4   = pool + 3200;      // [40][81][4] {c,c,s,s}; reused as reduction buf
    int bc = blockIdx.x;
    int spg = blockIdx.y;
    int t = threadIdx.x;
    int h0 = spg * 80;
    const float* base0 = S1p + (size_t)(bc * H_) * 40;
    const float* base1 = S1p + (size_t)(NROWS + bc * H_) * 40;

    for (int e = t; e < 1600; e += 800) {
        int hh = e / 20, kx = e % 20;
        float2 a = *(const float2*)&base0[(h0 + hh) * 40 + kx * 2];
        float2 b = *(const float2*)&base1[(h0 + hh) * 40 + kx * 2];
        s1re[hh * 20 + kx] = a.x + b.x;
        s1im[hh * 20 + kx] = a.y + b.y;
    }
    for (int e = t; e < 3200; e += 800) {
        int m = e / 80, hh = e % 80;
        float2 w = *(const float2*)&g_Wh[(m * H_ + h0 + hh) * 2];
        *(float4*)&w4[(m * 81 + hh) * 4] = make_float4(w.x, w.x, w.y, w.y);
    }
    __syncthreads();

    int sub = t / 100;           // 8 subtiles of 10 h
    int r = t % 100;
    int mg = r / 5;              // 20 m-groups of 2
    int kxg = r % 5;             // 5 kx-groups of 4 kx (2 u64 pairs)
    int m0 = mg * 2;
    u64 AR[2][2], AC[2][2], AS[2][2];
#pragma unroll
    for (int mi = 0; mi < 2; mi++)
#pragma unroll
        for (int j = 0; j < 2; j++) { AR[mi][j] = 0ULL; AC[mi][j] = 0ULL; AS[mi][j] = 0ULL; }

#pragma unroll
    for (int hh = 0; hh < 10; hh++) {
        int hl = sub * 10 + hh;
        ulonglong2 REq = *(const ulonglong2*)&s1re[hl * 20 + kxg * 4];
        ulonglong2 IMq = *(const ulonglong2*)&s1im[hl * 20 + kxg * 4];
#pragma unroll
        for (int mi = 0; mi < 2; mi++) {
            ulonglong2 wq = *(const ulonglong2*)&w4[((m0 + mi) * 81 + hl) * 4]; // {c,c},{s,s}
            fma2(AR[mi][0], REq.x, wq.x);
            fma2(AR[mi][1], REq.y, wq.x);
            fma2(AR[mi][0], IMq.x, wq.y);
            fma2(AR[mi][1], IMq.y, wq.y);
            fma2(AC[mi][0], IMq.x, wq.x);
            fma2(AC[mi][1], IMq.y, wq.x);
            fma2(AS[mi][0], REq.x, wq.y);
            fma2(AS[mi][1], REq.y, wq.y);
        }
    }
    __syncthreads();   // all w4 reads done; safe to overwrite with partials

    // each thread deposits its 16 result floats: j = mi*8 + jj*4 + q
#pragma unroll
    for (int mi = 0; mi < 2; mi++) {
#pragma unroll
        for (int jj = 0; jj < 2; jj++) {
            float ar0, ar1, c0, c1, s0, s1v;
            unpack2(AR[mi][jj], ar0, ar1);
            unpack2(AC[mi][jj], c0, c1);
            unpack2(AS[mi][jj], s0, s1v);
            float4 v = make_float4(ar0, c0 - s0, ar1, c1 - s1v);
            *(float4*)&w4[t * 16 + mi * 8 + jj * 4] = v;
        }
    }
    __syncthreads();

    // tree-reduce the 8 subtiles; thread t handles outputs t and t+800
    size_t obase = ((size_t)spg * BC + bc) * 1600;
#pragma unroll
    for (int gofs = 0; gofs < 2; gofs++) {
        int g = t + gofs * 800;
        int m = g / 40;
        int rem = g % 40;
        int kx2 = rem / 4;       // which 4-float group
        int q = rem % 4;
        int rr = (m / 2) * 5 + kx2 / 2;
        int j = (m % 2) * 8 + (kx2 % 2) * 4 + q;
        float a = 0.f;
#pragma unroll
        for (int sb = 0; sb < 8; sb++)
            a += w4[(sb * 100 + rr) * 16 + j];
        S2p[obase + g] = a;
    }
}

// ---------------- reduce split partials ----------------
__global__ void k_red(const float* __restrict__ P, float* __restrict__ S) {
    int t = blockIdx.x * blockDim.x + threadIdx.x;
    if (t >= BC * 1600) return;
    float a = 0.f;
#pragma unroll
    for (int p = 0; p < NPART; p++) a += P[(size_t)p * BC * 1600 + t];
    S[t] = a;
}

// ---------------- mode mixing ----------------
__global__ void k_mix(const float* __restrict__ S2, const float* __restrict__ fw1,
                      const float* __restrict__ fw2, int l, float* __restrict__ S3) {
    int t = blockIdx.x * blockDim.x + threadIdx.x;
    if (t >= Bb_ * C_ * NM * WN_ * 2) return;
    int z = t & 1;
    int kx = (t >> 1) % WN_;
    int m = ((t >> 1) / WN_) % NM;
    int o = ((t >> 1) / (WN_ * NM)) % C_;
    int b = t / (2 * WN_ * NM * C_);
    const float* wb;
    if (m < 20) wb = fw1 + l * 819200 + o * 800 + m * 40 + kx * 2 + z;
    else        wb = fw2 + l * 819200 + o * 800 + (m - 20) * 40 + kx * 2 + z;
    const float* s2 = S2 + (b * C_) * 1600 + m * (WN_ * 2) + kx * 2 + z;
    float acc = 0.f;
#pragma unroll 8
    for (int i = 0; i < C_; i++)
        acc += s2[i * 1600] * wb[i * 25600];
    S3[((b * C_ + o) * NM + m) * (WN_ * 2) + kx * 2 + z] = acc;
}

// ---------------- stage 1 inverse: ky synthesis (table twiddles) ----------------
__global__ void k_ifft_h(const float* __restrict__ S3, float* __restrict__ T) {
    int t = blockIdx.x * blockDim.x + threadIdx.x;
    if (t >= BC * H_ * WN_) return;
    int kx = t % WN_;
    int h = (t / WN_) % H_;
    int bc = t / (WN_ * H_);
    const float* s3 = S3 + bc * (NM * WN_ * 2) + kx * 2;
    float re = 0.f, im = 0.f;
#pragma unroll
    for (int m = 0; m < NM; m++) {
        float2 wt = *(const float2*)&g_Wh[(m * H_ + h) * 2];
        float ar = s3[m * (WN_ * 2)], ai = s3[m * (WN_ * 2) + 1];
        re += ar * wt.x - ai * wt.y;     // * e^{+i phi}
        im += ar * wt.y + ai * wt.x;
    }
    float sc = ((kx == 0) ? 1.0f : 2.0f) * (1.0f / 250000.0f);
    T[((size_t)bc * H_ + h) * 40 + kx * 2] = re * sc;
    T[((size_t)bc * H_ + h) * 40 + kx * 2 + 1] = im * sc;
}

// ---------------- stage 2 inverse + pointwise conv (augmented GEMM, 4w x 8o FFMA2) ----------------
// block = (wt, h, b), 160 threads; out[32 o][160 w] = [T|cw](32x72) x [Gi; Ain](72x160)
__global__ void __launch_bounds__(160) k_iw_conv(const float* __restrict__ T,
                                                 const float* __restrict__ Ain,
                                                 const float* __restrict__ cw,
                                                 const float* __restrict__ cb, int l,
                                                 float* __restrict__ Aout, int do_gelu) {
    __shared__ float R[72][160];
    __shared__ float Lh[72][32];
    int tid = threadIdx.x;
    int wt = blockIdx.x, h = blockIdx.y, b = blockIdx.z;
    int w0 = wt * 160;

    // staging with float4 loads
    for (int e = tid; e < 40 * 40; e += 160) {          // Gi: 40 rows x 40 float4
        int kz = e / 40, w4i = e % 40;
        *(float4*)&R[kz][w4i * 4] = *(const float4*)&g_Gi[kz * W_ + w0 + w4i * 4];
    }
    for (int e = tid; e < 32 * 40; e += 160) {          // Ain: 32 rows x 40 float4
        int i = e / 40, w4i = e % 40;
        *(float4*)&R[40 + i][w4i * 4] =
            *(const float4*)&Ain[((size_t)(b * C_ + i)) * NPIX + h * W_ + w0 + w4i * 4];
    }
    for (int e = tid; e < 40 * 32; e += 160) {
        int kz = e % 40, o = e / 40;
        Lh[kz][o] = T[((size_t)(b * C_ + o) * H_ + h) * 40 + kz];
    }
    for (int e = tid; e < 32 * 32; e += 160) {
        int i = e % 32, o = e / 32;
        Lh[40 + i][o] = cw[l * 1024 + o * 32 + i];
    }
    __syncthreads();

    int og = tid / 40;          // 4 o-groups of 8
    int wl = tid % 40;          // 4 pixels: wl + 40*q
    int o0 = og * 8;
    u64 aP[4][4];               // [q][o-pair]
#pragma unroll
    for (int p = 0; p < 4; p++) {
        u64 bias = pack2(cb[l * 32 + o0 + 2 * p], cb[l * 32 + o0 + 2 * p + 1]);
#pragma unroll
        for (int q = 0; q < 4; q++) aP[q][p] = bias;
    }

#pragma unroll 4
    for (int k = 0; k < 72; k++) {
        u64 r2[4];
#pragma unroll
        for (int q = 0; q < 4; q++) {
            float rv = R[k][wl + 40 * q];
            r2[q] = pack2(rv, rv);
        }
        ulonglong2 lq0 = *(const ulonglong2*)&Lh[k][o0];       // {L0,L1},{L2,L3}
        ulonglong2 lq1 = *(const ulonglong2*)&Lh[k][o0 + 4];   // {L4,L5},{L6,L7}
#pragma unroll
        for (int q = 0; q < 4; q++) {
            fma2(aP[q][0], r2[q], lq0.x);
            fma2(aP[q][1], r2[q], lq0.y);
            fma2(aP[q][2], r2[q], lq1.x);
            fma2(aP[q][3], r2[q], lq1.y);
        }
    }
#pragma unroll
    for (int p = 0; p < 4; p++) {
        size_t baseA = ((size_t)(b * C_ + o0 + 2 * p)) * NPIX + h * W_ + w0;
        size_t baseB = ((size_t)(b * C_ + o0 + 2 * p + 1)) * NPIX + h * W_ + w0;
#pragma unroll
        for (int q = 0; q < 4; q++) {
            float va, vb;
            unpack2(aP[q][p], va, vb);
            if (do_gelu) { va = gelu_f(va); vb = gelu_f(vb); }
            Aout[baseA + wl + 40 * q] = va;
            Aout[baseB + wl + 40 * q] = vb;
        }
    }
}

// ---------------- final: proj MLP + 3x3 mask conv + combine ----------------
__global__ void k_final(const float* __restrict__ A, const float* __restrict__ input,
                        const float* __restrict__ src,
                        const float* __restrict__ pw1, const float* __restrict__ pb1,
                        const float* __restrict__ pw2, const float* __restrict__ pb2,
                        const float* __restrict__ mw, const float* __restrict__ mb,
                        float* __restrict__ out) {
    int idx = blockIdx.x * blockDim.x + threadIdx.x;
    if (idx >= Bb_ * NPIX) return;
    int w = idx % W_;
    int h = (idx / W_) % H_;
    int b = idx / NPIX;

    const float* ap = A + (size_t)b * C_ * NPIX + h * W_ + w;
    float hid[16];
#pragma unroll
    for (int j = 0; j < 16; j++) hid[j] = pb1[j];
#pragma unroll 4
    for (int i = 0; i < 32; i++) {
        float av = ap[(size_t)i * NPIX];
#pragma unroll
        for (int j = 0; j < 16; j++) hid[j] += av * pw1[i * 16 + j];
    }
    float p0 = pb2[0], p1 = pb2[1];
#pragma unroll
    for (int j = 0; j < 16; j++) {
        float g = gelu_f(hid[j]);
        p0 += g * pw2[j * 2];
        p1 += g * pw2[j * 2 + 1];
    }
    float msum = mb[0];
#pragma unroll
    for (int dy = -1; dy <= 1; dy++) {
#pragma unroll
        for (int dx = -1; dx <= 1; dx++) {
            int hh = h + dy, ww = w + dx;
            if (hh >= 0 && hh < H_ && ww >= 0 && ww < W_)
                msum += input[(b * H_ + hh) * W_ + ww] * mw[(dy + 1) * 3 + (dx + 1)];
        }
    }
    const float* s = src + ((size_t)(b * H_ + h) * W_ + w) * 3;
    out[idx * 2 + 0] = s[1] * msum + p0;
    out[idx * 2 + 1] = s[2] * msum + p1;
}

// ---------------- launcher ----------------
extern "C" void kernel_launch(void* const* d_in, const int* in_sizes, int n_in,
                              void* d_out, int out_size) {
    const float* input = (const float*)d_in[0];
    const float* src   = (const float*)d_in[1];
    const float* iw1   = (const float*)d_in[2];
    const float* ib1   = (const float*)d_in[3];
    const float* iw2   = (const float*)d_in[4];
    const float* ib2   = (const float*)d_in[5];
    const float* ew1   = (const float*)d_in[6];
    const float* eb1   = (const float*)d_in[7];
    const float* ew2   = (const float*)d_in[8];
    const float* eb2   = (const float*)d_in[9];
    const float* fw1   = (const float*)d_in[10];
    const float* fw2   = (const float*)d_in[11];
    const float* cw    = (const float*)d_in[12];
    const float* cb    = (const float*)d_in[13];
    const float* pw1   = (const float*)d_in[14];
    const float* pb1   = (const float*)d_in[15];
    const float* pw2   = (const float*)d_in[16];
    const float* pb2   = (const float*)d_in[17];
    const float* mw    = (const float*)d_in[18];
    const float* mb    = (const float*)d_in[19];

    float *A, *Bp, *E, *S1, *S2p, *S2, *S3, *T;
    cudaGetSymbolAddress((void**)&A,   g_bufA);
    cudaGetSymbolAddress((void**)&Bp,  g_bufB);
    cudaGetSymbolAddress((void**)&E,   g_E);
    cudaGetSymbolAddress((void**)&S1,  g_S1);
    cudaGetSymbolAddress((void**)&S2p, g_S2p);
    cudaGetSymbolAddress((void**)&S2,  g_S2);
    cudaGetSymbolAddress((void**)&S3,  g_S3);
    cudaGetSymbolAddress((void**)&T,   g_T);

    k_tables<<<75, 256>>>();
    k_encode<<<(Bb_ * NPIX + 255) / 256, 256>>>(input, src, iw1, ib1, iw2, ib2,
                                                ew1, eb1, ew2, eb2, A, E);
    for (int l = 0; l < 4; l++) {
        float* Ain  = (l & 1) ? Bp : A;
        float* Aout = (l & 1) ? A  : Bp;
        dim3 gfw(NROWS / FW_BM, 2);
        k_fft_w<<<gfw, 160>>>(Ain, E, S1);
        dim3 gfh(BC, KSPLIT);
        k_fft_h<<<gfh, 800>>>(S1, S2p);
        k_red<<<(BC * 1600 + 255) / 256, 256>>>(S2p, S2);
        k_mix<<<(Bb_ * C_ * NM * WN_ * 2 + 255) / 256, 256>>>(S2, fw1, fw2, l, S3);
        k_ifft_h<<<(BC * H_ * WN_ + 255) / 256, 256>>>(S3, T);
        dim3 g(W_ / 160, H_, Bb_);
        k_iw_conv<<<g, 160>>>(T, Ain, cw, cb, l, Aout, (l < 3) ? 1 : 0);
    }
    k_final<<<(Bb_ * NPIX + 255) / 256, 256>>>(A, input, src, pw1, pb1, pw2, pb2,
                                               mw, mb, (float*)d_out);
}